// round 16
// baseline (speedup 1.0000x reference)
#include <cuda_runtime.h>

// Shape fixed by the reference
#define B_    8
#define T_    4096
#define D_    1024
#define L_    8                 // timesteps per chunk
#define NC_   (T_ / L_)         // 512 chunks per batch row
#define SUB_  2                 // chunks per block; overlap phase1b with lookback wait
#define NMEGA (NC_ / SUB_)      // 256 mega-items per chain
#define TPB   256               // 256 thr x float4 = D
#define NBLK  (B_ * NMEGA)      // 2048 blocks (power of 2 -> epoch = vid >> 11)
#define NITEM (B_ * NC_)        // 4096 chunk-level flag items
#define LB_P  16                // flags probed per round
#define LB_Q  4                 // aggregate loads per quad

#define SMEM_BYTES (L_ * TPB * 16)   // u payload of chunk 0 only: 32 KB

// Decoupled-lookback state (16 MB each -> L2-resident)
__device__ float    g_A[NITEM * D_];  // chunk aggregate: prod(a)
__device__ float    g_U[NITEM * D_];  // chunk aggregate: zero-carry scan tail
__device__ float    g_X[NITEM * D_];  // inclusive state after chunk
__device__ unsigned g_flag[NITEM];    // epoch-coded: 2e+1=aggregate, 2e+2=inclusive
__device__ unsigned g_ticket;         // never reset; epoch = ticket / NBLK

__device__ __forceinline__ float4 f4_fma(float4 a, float4 x, float4 u) {
    float4 r;
    r.x = fmaf(a.x, x.x, u.x); r.y = fmaf(a.y, x.y, u.y);
    r.z = fmaf(a.z, x.z, u.z); r.w = fmaf(a.w, x.w, u.w);
    return r;
}
__device__ __forceinline__ float4 f4_mul(float4 a, float4 b) {
    float4 r; r.x = a.x*b.x; r.y = a.y*b.y; r.z = a.z*b.z; r.w = a.w*b.w; return r;
}
__device__ __forceinline__ unsigned ld_acq(const unsigned* p) {
    unsigned v;
    asm volatile("ld.global.acquire.gpu.b32 %0, [%1];" : "=r"(v) : "l"(p) : "memory");
    return v;
}
__device__ __forceinline__ void st_rel(unsigned* p, unsigned v) {
    asm volatile("st.global.release.gpu.b32 [%0], %1;" :: "l"(p), "r"(v) : "memory");
}
__device__ __forceinline__ void st_stream(float4* p, float4 v) {
    asm volatile("st.global.cs.v4.f32 [%0], {%1,%2,%3,%4};"
                 :: "l"(p), "f"(v.x), "f"(v.y), "f"(v.z), "f"(v.w) : "memory");
}
__device__ __forceinline__ float4 ld_stream(const float4* p) {   // evict-first load
    float4 v;
    asm volatile("ld.global.cs.v4.f32 {%0,%1,%2,%3}, [%4];"
                 : "=f"(v.x), "=f"(v.y), "=f"(v.z), "=f"(v.w) : "l"(p));
    return v;
}

__global__ void __launch_bounds__(TPB, 4)
k_scan(const float* __restrict__ a,
       const float* __restrict__ u,
       const float* __restrict__ x0,
       float* __restrict__ out)
{
    extern __shared__ float4 sh_u[];        // [L_][TPB] u of chunk 0
    __shared__ unsigned sh_vid;
    __shared__ int sh_n[2];
    __shared__ int sh_inc[2];
    const int tid = threadIdx.x;

    if (tid == 0) sh_vid = atomicAdd(&g_ticket, 1u);
    __syncthreads();
    const unsigned vid   = sh_vid;
    const unsigned rel   = vid & (NBLK - 1u);   // mega-item within this launch
    const unsigned ebase = (vid >> 11) * 2u;    // epoch * 2 (flag base)
    const int b    = (int)(rel & (B_ - 1));     // round-robin chains across tickets
    const int mega = (int)(rel >> 3);
    const int c0   = mega * SUB_;
    const int d    = tid * 4;

    const long base0 = (((long)b * T_ + (long)c0 * L_) * D_ + d) >> 2;  // float4
    const long base1 = base0 + (long)L_ * (D_ / 4);
    const float4* __restrict__ ap0 = reinterpret_cast<const float4*>(a) + base0;
    const float4* __restrict__ up0 = reinterpret_cast<const float4*>(u) + base0;
    const float4* __restrict__ ap1 = reinterpret_cast<const float4*>(a) + base1;
    const float4* __restrict__ up1 = reinterpret_cast<const float4*>(u) + base1;

    float4* gA4 = reinterpret_cast<float4*>(g_A);
    float4* gU4 = reinterpret_cast<float4*>(g_U);
    float4* gX4 = reinterpret_cast<float4*>(g_X);
    const int item0 = b * NC_ + c0;
    const int item1 = item0 + 1;
    const int si0   = (item0 * D_ + d) >> 2;
    const int si1   = (item1 * D_ + d) >> 2;

    // ---- Phase 1a: chunk 0 — u evict-first into smem, a default (L2-warm for p4)
    float4 A0, U0;
    {
        float4 av = ap0[0];
        float4 uv = ld_stream(up0);
        if (c0 == 0) {   // fold x0 into u at global t=0
            float4 x0v = reinterpret_cast<const float4*>(x0)[(b * D_ + d) >> 2];
            uv = f4_fma(av, x0v, uv);
        }
        sh_u[tid] = uv;
        A0 = av; U0 = uv;
        #pragma unroll
        for (int t = 1; t < L_; ++t) {
            av = ap0[(long)t * (D_ / 4)];
            uv = ld_stream(up0 + (long)t * (D_ / 4));
            sh_u[t * TPB + tid] = uv;
            U0 = f4_fma(av, U0, uv);
            A0 = f4_mul(A0, av);
        }
    }
    if (c0 != 0) {                          // publish agg c0 ASAP (lookback invariant)
        gA4[si0] = A0;
        gU4[si0] = U0;
        __syncthreads();
        if (tid == 0) st_rel(&g_flag[item0], ebase + 1u);
    }

    // ---- Phase 1b: chunk 1 — default loads (L2-warm for phase 4b re-read).
    //      This streaming sits between agg-publish and lookback: hides the wait.
    float4 A1, U1;
    {
        float4 av = ap1[0];
        float4 uv = up1[0];
        A1 = av; U1 = uv;
        #pragma unroll
        for (int t = 1; t < L_; ++t) {
            av = ap1[(long)t * (D_ / 4)];
            uv = up1[(long)t * (D_ / 4)];
            U1 = f4_fma(av, U1, uv);
            A1 = f4_mul(A1, av);
        }
    }
    if (c0 != 0) {                          // publish agg c1 promptly as well
        gA4[si1] = A1;
        gU4[si1] = U1;
        __syncthreads();
        if (tid == 0) st_rel(&g_flag[item1], ebase + 1u);
    }

    // ---- Phase 2: single lookback for the carry into chunk 0
    float4 x_in = make_float4(0.f, 0.f, 0.f, 0.f);
    if (c0 != 0) {
        float4 As = make_float4(1.f, 1.f, 1.f, 1.f);
        float4 Us = make_float4(0.f, 0.f, 0.f, 0.f);
        int p = c0 - 1;
        int rb = 0;
        for (;;) {
            if (tid < 32) {
                const int lane = tid;
                const int pp = p - lane;
                int f = 0;
                if (lane < LB_P && pp >= 0)
                    f = (int)ld_acq(&g_flag[b * NC_ + pp]) - (int)ebase;  // 1=agg, 2=inc
                unsigned m1 = __ballot_sync(0xffffffffu, f >= 1) & 0xFFFFu;
                unsigned m2 = __ballot_sync(0xffffffffu, f == 2) & 0xFFFFu;
                if (lane == 0) {
                    unsigned gap = (~m1) & 0xFFFFu;
                    int navail = gap ? (__ffs(gap) - 1) : LB_P;   // consecutive ready
                    int linc   = m2 ? (__ffs(m2) - 1) : LB_P;     // first inclusive
                    if (linc < navail) { sh_n[rb] = linc; sh_inc[rb] = 1; }
                    else               { sh_n[rb] = navail; sh_inc[rb] = 0; }
                }
            }
            __syncthreads();
            const int n   = sh_n[rb];
            const int inc = sh_inc[rb];
            rb ^= 1;

            if (n == 0 && !inc) { __nanosleep(128); continue; }

            int remaining = n;
            int pi = ((b * NC_ + p) * D_ + d) >> 2;
            #pragma unroll
            for (int q = 0; q < LB_P / LB_Q; ++q) {
                if (remaining > 0) {
                    const int m = remaining < LB_Q ? remaining : LB_Q;
                    float4 Apq, Upq;
                    float4 Aq0, Uq0, Aq1, Uq1, Aq2, Uq2, Aq3, Uq3;
                    int pj = pi;
                    if (0 < m) { Aq0 = gA4[pj]; Uq0 = gU4[pj]; }  pj -= D_ / 4;
                    if (1 < m) { Aq1 = gA4[pj]; Uq1 = gU4[pj]; }  pj -= D_ / 4;
                    if (2 < m) { Aq2 = gA4[pj]; Uq2 = gU4[pj]; }  pj -= D_ / 4;
                    if (3 < m) { Aq3 = gA4[pj]; Uq3 = gU4[pj]; }
                    if (0 < m) { Us = f4_fma(As, Uq0, Us); As = f4_mul(As, Aq0); }
                    if (1 < m) { Us = f4_fma(As, Uq1, Us); As = f4_mul(As, Aq1); }
                    if (2 < m) { Us = f4_fma(As, Uq2, Us); As = f4_mul(As, Aq2); }
                    if (3 < m) { Us = f4_fma(As, Uq3, Us); As = f4_mul(As, Aq3); }
                    (void)Apq; (void)Upq;
                    pi -= m * (D_ / 4);
                    remaining -= m;
                }
            }
            if (inc) {
                float4 Xv = gX4[((b * NC_ + (p - n)) * D_ + d) >> 2];
                x_in = f4_fma(As, Xv, Us);
                break;
            }
            p -= n;
        }
    }

    // ---- Phase 3: publish both inclusives (one barrier, two releases)
    const float4 x_out0 = f4_fma(A0, x_in, U0);
    const float4 x_out1 = f4_fma(A1, x_out0, U1);
    gX4[si0] = x_out0;
    gX4[si1] = x_out1;
    __syncthreads();                        // gX stores visible before flag release
    if (tid == 0) {
        st_rel(&g_flag[item0], ebase + 2u);
        st_rel(&g_flag[item1], ebase + 2u);
    }

    // ---- Phase 4a: chunk 0 — a from L2, u from smem; outputs evict-first
    {
        float4* __restrict__ op = reinterpret_cast<float4*>(out) + base0;
        float4 x = x_in;
        #pragma unroll
        for (int t = 0; t < L_; ++t) {
            float4 av = ap0[(long)t * (D_ / 4)];
            float4 uv = sh_u[t * TPB + tid];
            x = f4_fma(av, x, uv);
            st_stream(op + (long)t * (D_ / 4), x);
        }
    }
    // ---- Phase 4b: chunk 1 — a and u from L2 (short window); outputs evict-first
    {
        float4* __restrict__ op = reinterpret_cast<float4*>(out) + base1;
        float4 x = x_out0;
        #pragma unroll
        for (int t = 0; t < L_; ++t) {
            float4 av = ap1[(long)t * (D_ / 4)];
            float4 uv = up1[(long)t * (D_ / 4)];
            x = f4_fma(av, x, uv);
            st_stream(op + (long)t * (D_ / 4), x);
        }
    }
}

extern "C" void kernel_launch(void* const* d_in, const int* in_sizes, int n_in,
                              void* d_out, int out_size) {
    const float* x0 = (const float*)d_in[0];
    const float* a  = (const float*)d_in[1];
    const float* u  = (const float*)d_in[2];
    float* out = (float*)d_out;

    cudaFuncSetAttribute(k_scan, cudaFuncAttributeMaxDynamicSharedMemorySize, SMEM_BYTES);
    k_scan<<<NBLK, TPB, SMEM_BYTES>>>(a, u, x0, out);   // epoch flags: no reset kernel
}

// round 17
// speedup vs baseline: 1.5384x; 1.5384x over previous
#include <cuda_runtime.h>

// Shape fixed by the reference
#define B_   8
#define T_   4096
#define D_   1024
#define L_   16                // timesteps per chunk; a re-read from L2, u from smem
#define NC_  (T_ / L_)         // 256 chunks per batch row
#define TPB  256               // 256 thr x float4 = D
#define NBLK (B_ * NC_)        // 2048 blocks (power of 2 -> epoch = vid >> 11)
#define LB_P 8                 // flags probed per round
#define LB_Q 4                 // aggregate loads per quad
#define BATCH 8                // phase-1 load batch (MLP = 16 float4 in flight)

#define SMEM_BYTES (L_ * TPB * 16)   // u payload: 64 KB

// Decoupled-lookback state (8 MB each -> L2-resident)
__device__ float    g_A[NBLK * D_];   // chunk aggregate: prod(a)
__device__ float    g_U[NBLK * D_];   // chunk aggregate: zero-carry scan tail
__device__ float    g_X[NBLK * D_];   // inclusive state after chunk
__device__ unsigned g_flag[NBLK];     // epoch-coded: 2e+1=aggregate, 2e+2=inclusive
__device__ unsigned g_ticket;         // never reset; epoch = ticket / NBLK

__device__ __forceinline__ float4 f4_fma(float4 a, float4 x, float4 u) {
    float4 r;
    r.x = fmaf(a.x, x.x, u.x); r.y = fmaf(a.y, x.y, u.y);
    r.z = fmaf(a.z, x.z, u.z); r.w = fmaf(a.w, x.w, u.w);
    return r;
}
__device__ __forceinline__ float4 f4_mul(float4 a, float4 b) {
    float4 r; r.x = a.x*b.x; r.y = a.y*b.y; r.z = a.z*b.z; r.w = a.w*b.w; return r;
}
__device__ __forceinline__ unsigned ld_acq(const unsigned* p) {
    unsigned v;
    asm volatile("ld.global.acquire.gpu.b32 %0, [%1];" : "=r"(v) : "l"(p) : "memory");
    return v;
}
__device__ __forceinline__ void st_rel(unsigned* p, unsigned v) {
    asm volatile("st.global.release.gpu.b32 [%0], %1;" :: "l"(p), "r"(v) : "memory");
}
__device__ __forceinline__ void st_stream(float4* p, float4 v) {
    asm volatile("st.global.cs.v4.f32 [%0], {%1,%2,%3,%4};"
                 :: "l"(p), "f"(v.x), "f"(v.y), "f"(v.z), "f"(v.w) : "memory");
}
__device__ __forceinline__ float4 ld_stream(const float4* p) {   // evict-first load
    float4 v;
    asm volatile("ld.global.cs.v4.f32 {%0,%1,%2,%3}, [%4];"
                 : "=f"(v.x), "=f"(v.y), "=f"(v.z), "=f"(v.w) : "l"(p));
    return v;
}

__global__ void __launch_bounds__(TPB, 3)
k_scan(const float* __restrict__ a,
       const float* __restrict__ u,
       const float* __restrict__ x0,
       float* __restrict__ out)
{
    extern __shared__ float4 sh_u[];        // [L_][TPB] u payload
    __shared__ unsigned sh_vid;
    __shared__ int sh_n[2];
    __shared__ int sh_inc[2];
    const int tid = threadIdx.x;

    if (tid == 0) sh_vid = atomicAdd(&g_ticket, 1u);
    __syncthreads();
    const unsigned vid   = sh_vid;
    const unsigned rel   = vid & (NBLK - 1u);   // item within this launch
    const unsigned ebase = (vid >> 11) * 2u;    // epoch * 2 (flag base)
    const int b = (int)(rel & (B_ - 1));        // round-robin b across tickets
    const int c = (int)(rel >> 3);
    const int d = tid * 4;

    const long base = (((long)b * T_ + (long)c * L_) * D_ + d) >> 2;  // float4 units
    const float4* __restrict__ ap = reinterpret_cast<const float4*>(a) + base;
    const float4* __restrict__ up = reinterpret_cast<const float4*>(u) + base;

    // ---- Phase 1: stream chunk in two 8-deep batches (16 float4 loads in flight)
    float4 A, U;
    {
        float4 avb[BATCH], uvb[BATCH];
        // batch 0: t = 0..7
        #pragma unroll
        for (int t = 0; t < BATCH; ++t) avb[t] = ap[(long)t * (D_ / 4)];
        #pragma unroll
        for (int t = 0; t < BATCH; ++t) uvb[t] = ld_stream(up + (long)t * (D_ / 4));
        if (c == 0) {   // fold x0 into u at global t=0
            float4 x0v = reinterpret_cast<const float4*>(x0)[(b * D_ + d) >> 2];
            uvb[0] = f4_fma(avb[0], x0v, uvb[0]);
        }
        #pragma unroll
        for (int t = 0; t < BATCH; ++t) sh_u[t * TPB + tid] = uvb[t];
        A = avb[0]; U = uvb[0];
        #pragma unroll
        for (int t = 1; t < BATCH; ++t) {
            U = f4_fma(avb[t], U, uvb[t]);
            A = f4_mul(A, avb[t]);
        }
        // batch 1: t = 8..15
        #pragma unroll
        for (int t = 0; t < BATCH; ++t) avb[t] = ap[(long)(BATCH + t) * (D_ / 4)];
        #pragma unroll
        for (int t = 0; t < BATCH; ++t) uvb[t] = ld_stream(up + (long)(BATCH + t) * (D_ / 4));
        #pragma unroll
        for (int t = 0; t < BATCH; ++t) sh_u[(BATCH + t) * TPB + tid] = uvb[t];
        #pragma unroll
        for (int t = 0; t < BATCH; ++t) {
            U = f4_fma(avb[t], U, uvb[t]);
            A = f4_mul(A, avb[t]);
        }
    }

    float4* gA4 = reinterpret_cast<float4*>(g_A);
    float4* gU4 = reinterpret_cast<float4*>(g_U);
    float4* gX4 = reinterpret_cast<float4*>(g_X);
    const int si = ((b * NC_ + c) * D_ + d) >> 2;

    float4 x_in = make_float4(0.f, 0.f, 0.f, 0.f);

    if (c == 0) {
        gX4[si] = U;                       // inclusive known immediately
        __syncthreads();                   // all block stores done before release
        if (tid == 0) st_rel(&g_flag[b * NC_], ebase + 2u);
    } else {
        // publish aggregate ASAP
        gA4[si] = A;
        gU4[si] = U;
        __syncthreads();
        if (tid == 0) st_rel(&g_flag[b * NC_ + c], ebase + 1u);

        // ---- Phase 2: lookback — probe 8 flags/round, consume in 4-wide quads
        float4 As = make_float4(1.f, 1.f, 1.f, 1.f);
        float4 Us = make_float4(0.f, 0.f, 0.f, 0.f);
        int p = c - 1;
        int rb = 0;                        // double-buffer selector
        for (;;) {
            if (tid < 32) {
                const int lane = tid;
                const int pp = p - lane;
                int f = 0;
                if (lane < LB_P && pp >= 0)
                    f = (int)ld_acq(&g_flag[b * NC_ + pp]) - (int)ebase;  // 1=agg, 2=inc
                unsigned m1 = __ballot_sync(0xffffffffu, f >= 1) & ((1u << LB_P) - 1u);
                unsigned m2 = __ballot_sync(0xffffffffu, f == 2) & ((1u << LB_P) - 1u);
                if (lane == 0) {
                    unsigned gap = (~m1) & ((1u << LB_P) - 1u);
                    int navail = gap ? (__ffs(gap) - 1) : LB_P;   // consecutive published
                    int linc   = m2 ? (__ffs(m2) - 1) : LB_P;     // first inclusive slot
                    if (linc < navail) { sh_n[rb] = linc; sh_inc[rb] = 1; }
                    else               { sh_n[rb] = navail; sh_inc[rb] = 0; }
                }
            }
            __syncthreads();               // one barrier per round (buffers alternate)
            const int n   = sh_n[rb];
            const int inc = sh_inc[rb];
            rb ^= 1;

            if (n == 0 && !inc) { __nanosleep(128); continue; }

            // consume n predecessors in up-to-two 4-wide quads
            int remaining = n;
            int pi = ((b * NC_ + p) * D_ + d) >> 2;
            #pragma unroll
            for (int q = 0; q < LB_P / LB_Q; ++q) {
                if (remaining > 0) {
                    const int m = remaining < LB_Q ? remaining : LB_Q;
                    float4 Ap0, Up0, Ap1, Up1, Ap2, Up2, Ap3, Up3;
                    int pj = pi;
                    if (0 < m) { Ap0 = gA4[pj]; Up0 = gU4[pj]; }  pj -= D_ / 4;
                    if (1 < m) { Ap1 = gA4[pj]; Up1 = gU4[pj]; }  pj -= D_ / 4;
                    if (2 < m) { Ap2 = gA4[pj]; Up2 = gU4[pj]; }  pj -= D_ / 4;
                    if (3 < m) { Ap3 = gA4[pj]; Up3 = gU4[pj]; }
                    if (0 < m) { Us = f4_fma(As, Up0, Us); As = f4_mul(As, Ap0); }
                    if (1 < m) { Us = f4_fma(As, Up1, Us); As = f4_mul(As, Ap1); }
                    if (2 < m) { Us = f4_fma(As, Up2, Us); As = f4_mul(As, Ap2); }
                    if (3 < m) { Us = f4_fma(As, Up3, Us); As = f4_mul(As, Ap3); }
                    pi -= m * (D_ / 4);
                    remaining -= m;
                }
            }
            if (inc) {
                float4 Xv = gX4[((b * NC_ + (p - n)) * D_ + d) >> 2];
                x_in = f4_fma(As, Xv, Us);
                break;
            }
            p -= n;
        }

        // ---- Phase 3: publish inclusive (unblocks successors before phase 4)
        gX4[si] = f4_fma(A, x_in, U);
        __syncthreads();
        if (tid == 0) st_rel(&g_flag[b * NC_ + c], ebase + 2u);
    }

    // ---- Phase 4: a from L2 (protected window), u from smem; stores evict-first
    float4* __restrict__ op = reinterpret_cast<float4*>(out) + base;
    float4 x = x_in;
    #pragma unroll 4
    for (int t = 0; t < L_; ++t) {
        float4 av = ap[(long)t * (D_ / 4)];
        float4 uv = sh_u[t * TPB + tid];
        x = f4_fma(av, x, uv);
        st_stream(op + (long)t * (D_ / 4), x);
    }
}

extern "C" void kernel_launch(void* const* d_in, const int* in_sizes, int n_in,
                              void* d_out, int out_size) {
    const float* x0 = (const float*)d_in[0];
    const float* a  = (const float*)d_in[1];
    const float* u  = (const float*)d_in[2];
    float* out = (float*)d_out;

    cudaFuncSetAttribute(k_scan, cudaFuncAttributeMaxDynamicSharedMemorySize, SMEM_BYTES);
    k_scan<<<NBLK, TPB, SMEM_BYTES>>>(a, u, x0, out);   // epoch flags: no reset kernel
}